// round 1
// baseline (speedup 1.0000x reference)
#include <cuda_runtime.h>
#include <math.h>

#define BB 48
#define SS 128
#define WW 4
#define KK 256

// Precomputed exp(T * tag_mask), transposed: g_expTt[b][kp][k]
__device__ float g_expTt[BB * KK * KK];

// ---------------------------------------------------------------------------
// Prep: expTt[b][kp][k] = exp(T[b][k][kp] * tag_mask[b][k][kp])  (tiled transpose)
// ---------------------------------------------------------------------------
__global__ __launch_bounds__(256) void prep_kernel(const float* __restrict__ T,
                                                   const float* __restrict__ tagm) {
    __shared__ float tile[32][33];
    const int b   = blockIdx.z;
    const int kp0 = blockIdx.x * 32;   // T column block
    const int k0  = blockIdx.y * 32;   // T row block
    const int x = threadIdx.x;         // 0..31
    const int y = threadIdx.y;         // 0..7
    const size_t base = (size_t)b * KK * KK;

    #pragma unroll
    for (int i = y; i < 32; i += 8) {
        size_t idx = base + (size_t)(k0 + i) * KK + (kp0 + x);
        tile[i][x] = __expf(T[idx] * tagm[idx]);
    }
    __syncthreads();
    #pragma unroll
    for (int i = y; i < 32; i += 8) {
        // value for (k = k0+x, kp = kp0+i) is tile[x][i]
        g_expTt[base + (size_t)(kp0 + i) * KK + (k0 + x)] = tile[x][i];
    }
}

// ---------------------------------------------------------------------------
// Main: one block per batch b, 256 threads = one per label k.
// Sequential over j; per step a K x K x W exp-domain mat-vec.
// ---------------------------------------------------------------------------
__global__ __launch_bounds__(256) void crf_kernel(
    const float* __restrict__ logits,
    const float* __restrict__ hc,
    const float* __restrict__ tagm,
    const int*   __restrict__ textmask,
    float* __restrict__ out)
{
    __shared__ float4 sV[KK];     // sV[kp] = exp(alpha_{j-1-w}[kp] - m_w) for w=0..3
    __shared__ float  sM[4];      // per-history-row max
    __shared__ float  sred[16];   // reduction scratch

    const int b    = blockIdx.x;
    const int k    = threadIdx.x;
    const int lane = k & 31;
    const int wid  = k >> 5;

    // ---- length[b] = sum(text_mask[b, :]) ----
    int t = (k < SS) ? textmask[b * SS + k] : 0;
    #pragma unroll
    for (int o = 16; o; o >>= 1) t += __shfl_xor_sync(0xffffffffu, t, o);
    if (lane == 0) sred[wid] = (float)t;
    __syncthreads();
    int L = 0;
    #pragma unroll
    for (int i = 0; i < 8; i++) L += (int)sred[i];
    __syncthreads();

    if (L == 0) {                       // partition = lse(zeros) = log K
        if (k == 0) out[b] = logf(256.0f);
        return;
    }

    const float tm0 = tagm[(size_t)b * KK * KK + k];     // tag_mask[b, 0, k]
    const float* Tt = g_expTt + (size_t)b * KK * KK;     // [kp][k]

    float h[4];                          // alpha history for this k (ring, idx = j&3)
    const int JMAX = (L < SS) ? L : SS;  // alphas beyond L-1 never used

    for (int j = 0; j < JMAX; j++) {
        // ---- emission: emit[w,k] = (logits + hamming) * tag_mask[b,0,k] ----
        float e[WW];
        const size_t ebase = (((size_t)b * SS + j) * WW) * KK + k;
        #pragma unroll
        for (int w = 0; w < WW; w++)
            e[w] = (logits[ebase + (size_t)w * KK] + hc[ebase + (size_t)w * KK]) * tm0;

        const int nT = (j < WW) ? j : WW;    // #w with a real transition (w < j)
        float M = (j < WW) ? 0.0f : -1e30f;  // zero-row max is 0 when present
        float mloc[WW];
        #pragma unroll
        for (int w = 0; w < WW; w++) {
            if (w < nT) { mloc[w] = sM[(j - 1 - w) & 3]; M = fmaxf(M, mloc[w]); }
            else mloc[w] = 0.0f;
        }

        // ---- build v rows (own k only; invalid w -> 0 so FMA is a no-op) ----
        float v0 = 0.f, v1 = 0.f, v2 = 0.f, v3 = 0.f;
        if (0 < nT) v0 = __expf(h[(j - 1) & 3] - mloc[0]);
        if (1 < nT) v1 = __expf(h[(j - 2) & 3] - mloc[1]);
        if (2 < nT) v2 = __expf(h[(j - 3) & 3] - mloc[2]);
        if (3 < nT) v3 = __expf(h[(j - 4) & 3] - mloc[3]);
        sV[k] = make_float4(v0, v1, v2, v3);
        __syncthreads();

        // ---- dot_w[k] = sum_kp expT'[k,kp] * v_w[kp] ----
        float a0 = 0.f, a1 = 0.f, a2 = 0.f, a3 = 0.f;
        #pragma unroll 8
        for (int kp = 0; kp < KK; kp++) {
            const float tv = __ldg(&Tt[(size_t)kp * KK + k]);  // coalesced, L2-hot
            const float4 v = sV[kp];                            // smem broadcast
            a0 += tv * v.x;
            a1 += tv * v.y;
            a2 += tv * v.z;
            a3 += tv * v.w;
        }
        float acc[WW] = {a0, a1, a2, a3};

        // ---- combine over w ----
        float tot = 0.0f;
        #pragma unroll
        for (int w = 0; w < WW; w++)
            if (w < nT) tot += __expf(e[w] + mloc[w] - M) * acc[w];
        if (j < WW) tot += 256.0f * __expf(e[j] - M);   // initial-state (zero) row

        const float a = M + __logf(tot);
        h[j & 3] = a;

        // ---- block max of new alpha row ----
        float mv = a;
        #pragma unroll
        for (int o = 16; o; o >>= 1) mv = fmaxf(mv, __shfl_xor_sync(0xffffffffu, mv, o));
        __syncthreads();                    // dot-loop sV reads done; sred free
        if (lane == 0) sred[wid] = mv;
        __syncthreads();
        float rowmax = sred[0];
        #pragma unroll
        for (int i = 1; i < 8; i++) rowmax = fmaxf(rowmax, sred[i]);
        if (k == 0) sM[j & 3] = rowmax;

        // ---- final logsumexp over k at j = L-1 ----
        if (j + 1 == JMAX) {
            float sv = __expf(a - rowmax);
            #pragma unroll
            for (int o = 16; o; o >>= 1) sv += __shfl_xor_sync(0xffffffffu, sv, o);
            if (lane == 0) sred[8 + wid] = sv;
            __syncthreads();
            if (k == 0) {
                float ssum = 0.f;
                #pragma unroll
                for (int i = 0; i < 8; i++) ssum += sred[8 + i];
                out[b] = rowmax + __logf(ssum);
            }
        }
        __syncthreads();   // orders sM write / sV rewrite for next iteration
    }
}

// ---------------------------------------------------------------------------
extern "C" void kernel_launch(void* const* d_in, const int* in_sizes, int n_in,
                              void* d_out, int out_size) {
    const float* logits = (const float*)d_in[0];   // (B,S,W,K) f32
    const float* T      = (const float*)d_in[1];   // (B,K,K)   f32
    const float* hc     = (const float*)d_in[2];   // (B,S,W,K) f32
    const float* tagm   = (const float*)d_in[3];   // (B,K,K)   f32
    const int*   tmask  = (const int*)  d_in[4];   // (B,S)     i32
    float* out = (float*)d_out;                    // (1,B)     f32

    dim3 pb(32, 8);
    dim3 pg(KK / 32, KK / 32, BB);
    prep_kernel<<<pg, pb>>>(T, tagm);
    crf_kernel<<<BB, 256>>>(logits, hc, tagm, tmask, out);
}

// round 2
// speedup vs baseline: 5.6350x; 5.6350x over previous
#include <cuda_runtime.h>
#include <math.h>

#define BB 48
#define SS 128
#define WW 4
#define KK 256
#define NTHREADS 512
#define NGROUPS 8
#define KP_PER_G (KK / NGROUPS)   // 32

typedef unsigned long long ull;

// Precomputed exp(T * tag_mask), transposed: g_expTt[b][kp][k]
__device__ float g_expTt[BB * KK * KK];

#define FMA2(acc, a, b) \
    asm("fma.rn.f32x2 %0, %1, %2, %0;" : "+l"(acc) : "l"(a), "l"(b))
#define UNPACK2(lo, hi, p) \
    asm("mov.b64 {%0, %1}, %2;" : "=f"(lo), "=f"(hi) : "l"(p))

// ---------------------------------------------------------------------------
// Prep: expTt[b][kp][k] = exp(T[b][k][kp] * tag_mask[b][k][kp])
// ---------------------------------------------------------------------------
__global__ __launch_bounds__(256) void prep_kernel(const float* __restrict__ T,
                                                   const float* __restrict__ tagm) {
    __shared__ float tile[32][33];
    const int b   = blockIdx.z;
    const int kp0 = blockIdx.x * 32;
    const int k0  = blockIdx.y * 32;
    const int x = threadIdx.x;
    const int y = threadIdx.y;
    const size_t base = (size_t)b * KK * KK;

    #pragma unroll
    for (int i = y; i < 32; i += 8) {
        size_t idx = base + (size_t)(k0 + i) * KK + (kp0 + x);
        tile[i][x] = __expf(T[idx] * tagm[idx]);
    }
    __syncthreads();
    #pragma unroll
    for (int i = y; i < 32; i += 8) {
        g_expTt[base + (size_t)(kp0 + i) * KK + (k0 + x)] = tile[x][i];
    }
}

// ---------------------------------------------------------------------------
// Main: one block per batch. 512 threads: 8 groups x 64 threads for the
// K x K x W exp-domain mat-vec (f32x2 packed FFMA), 256 threads (=k) for
// the per-label logsumexp bookkeeping.
// ---------------------------------------------------------------------------
__global__ __launch_bounds__(NTHREADS) void crf_kernel(
    const float* __restrict__ logits,
    const float* __restrict__ hc,
    const float* __restrict__ tagm,
    const int*   __restrict__ textmask,
    float* __restrict__ out)
{
    __shared__ float4 sVd[KK][2];           // [(v0,v0,v1,v1),(v2,v2,v3,v3)] per kp
    __shared__ float4 sPart[NGROUPS][KK];   // partial dot per group, (w0..w3)
    __shared__ float  sred[16];

    const int tid  = threadIdx.x;
    const int b    = blockIdx.x;
    const int lane = tid & 31;
    const int wid  = tid >> 5;
    const int g    = tid >> 6;      // group 0..7
    const int u    = tid & 63;      // column quad within group

    // ---- length[b] ----
    int t = (tid < SS) ? textmask[b * SS + tid] : 0;
    #pragma unroll
    for (int o = 16; o; o >>= 1) t += __shfl_xor_sync(0xffffffffu, t, o);
    if (lane == 0) sred[wid] = (float)t;
    __syncthreads();
    int L = 0;
    #pragma unroll
    for (int i = 0; i < 16; i++) L += (int)sred[i];
    __syncthreads();
    if (L == 0) { if (tid == 0) out[b] = logf(256.0f); return; }
    const int JMAX = (L < SS) ? L : SS;

    const ulonglong2* __restrict__ Tt2 =
        (const ulonglong2*)(g_expTt + (size_t)b * KK * KK);  // 64 u2 per kp row
    const ulonglong2* __restrict__ tbase = Tt2 + (size_t)(g * KP_PER_G) * 64 + u;
    const ulonglong2* __restrict__ svd2 = (const ulonglong2*)&sVd[0][0];

    const int k = tid;  // label index, valid when tid < KK
    float tm0 = 0.0f;
    float eb0 = 0.f, eb1 = 0.f, eb2 = 0.f, eb3 = 0.f;   // emissions for step j
    float h0, h1, h2, h3;                               // alpha history (regs)
    float m0, m1, m2, m3;                               // rowmax history (regs)
    h0 = h1 = h2 = h3 = 0.f; m0 = m1 = m2 = m3 = 0.f;

    if (tid < KK) {
        tm0 = tagm[(size_t)b * KK * KK + k];
        const size_t e0i = ((size_t)b * SS) * WW * KK + k;
        eb0 = (logits[e0i          ] + hc[e0i          ]) * tm0;
        eb1 = (logits[e0i + 1 * KK ] + hc[e0i + 1 * KK ]) * tm0;
        eb2 = (logits[e0i + 2 * KK ] + hc[e0i + 2 * KK ]) * tm0;
        eb3 = (logits[e0i + 3 * KK ] + hc[e0i + 3 * KK ]) * tm0;
    }

    for (int j = 0; j < JMAX; j++) {
        const int nT = (j < WW) ? j : WW;

        // ---- phase A: build v rows, history maxes ----
        float M = (j < WW) ? 0.0f : -1e30f;
        if (tid < KK) {
            float v0 = 0.f, v1 = 0.f, v2 = 0.f, v3 = 0.f;
            if (nT > 0) { v0 = __expf(h0 - m0); M = fmaxf(M, m0); }
            if (nT > 1) { v1 = __expf(h1 - m1); M = fmaxf(M, m1); }
            if (nT > 2) { v2 = __expf(h2 - m2); M = fmaxf(M, m2); }
            if (nT > 3) { v3 = __expf(h3 - m3); M = fmaxf(M, m3); }
            sVd[k][0] = make_float4(v0, v0, v1, v1);
            sVd[k][1] = make_float4(v2, v2, v3, v3);
        }
        __syncthreads();

        // ---- prefetch next step's emissions (hidden under the mat-vec) ----
        float lb0 = 0.f, lb1 = 0.f, lb2 = 0.f, lb3 = 0.f;
        float hb0 = 0.f, hb1 = 0.f, hb2 = 0.f, hb3 = 0.f;
        if (tid < KK && (j + 1) < JMAX) {
            const size_t ei = (((size_t)b * SS + (j + 1)) * WW) * KK + k;
            lb0 = logits[ei];          hb0 = hc[ei];
            lb1 = logits[ei + 1 * KK]; hb1 = hc[ei + 1 * KK];
            lb2 = logits[ei + 2 * KK]; hb2 = hc[ei + 2 * KK];
            lb3 = logits[ei + 3 * KK]; hb3 = hc[ei + 3 * KK];
        }

        // ---- phase B: packed-f32x2 mat-vec over my kp slice ----
        ull a00 = 0, a01 = 0, a02 = 0, a03 = 0;   // k-pair (4u, 4u+1), w=0..3
        ull a10 = 0, a11 = 0, a12 = 0, a13 = 0;   // k-pair (4u+2, 4u+3)
        const int kp0 = g * KP_PER_G;
        #pragma unroll 8
        for (int i = 0; i < KP_PER_G; i++) {
            ulonglong2 tv  = __ldg(tbase + (size_t)i * 64);
            ulonglong2 vd0 = svd2[(kp0 + i) * 2 + 0];
            ulonglong2 vd1 = svd2[(kp0 + i) * 2 + 1];
            FMA2(a00, tv.x, vd0.x);  FMA2(a10, tv.y, vd0.x);
            FMA2(a01, tv.x, vd0.y);  FMA2(a11, tv.y, vd0.y);
            FMA2(a02, tv.x, vd1.x);  FMA2(a12, tv.y, vd1.x);
            FMA2(a03, tv.x, vd1.y);  FMA2(a13, tv.y, vd1.y);
        }
        // unpack and write partials
        {
            float f00, f10, f20, f30, f01, f11, f21, f31;
            float f02, f12, f22, f32, f03, f13, f23, f33;
            UNPACK2(f00, f10, a00);  UNPACK2(f20, f30, a10);
            UNPACK2(f01, f11, a01);  UNPACK2(f21, f31, a11);
            UNPACK2(f02, f12, a02);  UNPACK2(f22, f32, a12);
            UNPACK2(f03, f13, a03);  UNPACK2(f23, f33, a13);
            sPart[g][4 * u + 0] = make_float4(f00, f01, f02, f03);
            sPart[g][4 * u + 1] = make_float4(f10, f11, f12, f13);
            sPart[g][4 * u + 2] = make_float4(f20, f21, f22, f23);
            sPart[g][4 * u + 3] = make_float4(f30, f31, f32, f33);
        }
        __syncthreads();

        // ---- phase C1: combine, compute alpha, start rowmax reduce ----
        float a = 0.f;
        if (tid < KK) {
            float4 s = sPart[0][k];
            float aw0 = s.x, aw1 = s.y, aw2 = s.z, aw3 = s.w;
            #pragma unroll
            for (int gg = 1; gg < NGROUPS; gg++) {
                float4 p = sPart[gg][k];
                aw0 += p.x; aw1 += p.y; aw2 += p.z; aw3 += p.w;
            }
            float tot = 0.0f;
            if (nT > 0) tot += __expf(eb0 + m0 - M) * aw0;
            if (nT > 1) tot += __expf(eb1 + m1 - M) * aw1;
            if (nT > 2) tot += __expf(eb2 + m2 - M) * aw2;
            if (nT > 3) tot += __expf(eb3 + m3 - M) * aw3;
            if (j < WW) {   // initial-state (zero) row at w == j
                float einit = (j == 0) ? eb0 : (j == 1) ? eb1 : (j == 2) ? eb2 : eb3;
                tot += 256.0f * __expf(einit - M);
            }
            a = M + __logf(tot);

            float mv = a;
            #pragma unroll
            for (int o = 16; o; o >>= 1)
                mv = fmaxf(mv, __shfl_xor_sync(0xffffffffu, mv, o));
            if (lane == 0) sred[wid] = mv;
        }
        __syncthreads();

        // ---- phase C2: finish rowmax, shift history, roll emissions ----
        if (tid < KK) {
            float rowmax = sred[0];
            #pragma unroll
            for (int i = 1; i < 8; i++) rowmax = fmaxf(rowmax, sred[i]);
            m3 = m2; m2 = m1; m1 = m0; m0 = rowmax;
            h3 = h2; h2 = h1; h1 = h0; h0 = a;
            eb0 = (lb0 + hb0) * tm0;
            eb1 = (lb1 + hb1) * tm0;
            eb2 = (lb2 + hb2) * tm0;
            eb3 = (lb3 + hb3) * tm0;
            if (j + 1 == JMAX) {        // final logsumexp over k
                float sv = __expf(a - rowmax);
                #pragma unroll
                for (int o = 16; o; o >>= 1)
                    sv += __shfl_xor_sync(0xffffffffu, sv, o);
                if (lane == 0) sred[8 + wid] = sv;
            }
        }
        __syncthreads();
    }

    if (tid == 0) {
        float rowmax = sred[0];
        #pragma unroll
        for (int i = 1; i < 8; i++) rowmax = fmaxf(rowmax, sred[i]);
        float ssum = 0.f;
        #pragma unroll
        for (int i = 0; i < 8; i++) ssum += sred[8 + i];
        out[b] = rowmax + __logf(ssum);
    }
}

// ---------------------------------------------------------------------------
extern "C" void kernel_launch(void* const* d_in, const int* in_sizes, int n_in,
                              void* d_out, int out_size) {
    const float* logits = (const float*)d_in[0];   // (B,S,W,K) f32
    const float* T      = (const float*)d_in[1];   // (B,K,K)   f32
    const float* hc     = (const float*)d_in[2];   // (B,S,W,K) f32
    const float* tagm   = (const float*)d_in[3];   // (B,K,K)   f32
    const int*   tmask  = (const int*)  d_in[4];   // (B,S)     i32
    float* out = (float*)d_out;                    // (1,B)     f32

    dim3 pb(32, 8);
    dim3 pg(KK / 32, KK / 32, BB);
    prep_kernel<<<pg, pb>>>(T, tagm);
    crf_kernel<<<BB, NTHREADS>>>(logits, hc, tagm, tmask, out);
}